// round 7
// baseline (speedup 1.0000x reference)
#include <cuda_runtime.h>
#include <cuda_bf16.h>

// BPMLL loss — tail-free single compute kernel + memset graph node.
//   Graph: [memset d_out=0] -> [bpmll_kernel].
//   256 blocks x 256 threads; 128 threads per row (2 rows/block), 4 elems/thread.
//   Row reduce: two interleaved shfl_xor butterfly chains (pos/neg overlap);
//   label count via ballot+popc (no integer shuffle chain). Row leader fires
//   red.global.add.f32 of part/512 straight into d_out and the block exits —
//   no counter, no winner block, no second reduction phase.
//
// Math per element (2 MUFU + 4 FMA):
//   exp(-sigmoid(c)) = e^{-1} * exp(sigmoid(-c)) -> h(x)=exp(sigmoid(x)),
//   x = y ? -c : c. sigmoid = EX2+RCP; exp(s), s in (0,1), degree-4 poly.

#define ROWS 512
#define COLS 512
#define NBLK 256
#define TPB  256

#define D0 1.00002694f
#define D1 0.99871530f
#define D2 0.50996560f
#define D3 0.13998530f
#define D4 0.06956140f
#define E_INV_OVER_ROWS (0.36787944117144233f / 512.0f)

__device__ __forceinline__ void elem(float c, int y, float& pos, float& neg) {
    float x = __int_as_float(__float_as_int(c) ^ (y << 31));  // y ? -c : c
    float t = __expf(-x);                                     // MUFU.EX2
    float s;
    asm("rcp.approx.f32 %0, %1;" : "=f"(s) : "f"(1.0f + t));  // MUFU.RCP
    float h = fmaf(s, D4, D3);
    h = fmaf(h, s, D2);
    h = fmaf(h, s, D1);
    h = fmaf(h, s, D0);
    if (y) pos += h; else neg += h;
}

__global__ __launch_bounds__(TPB) void bpmll_kernel(const float* __restrict__ c,
                                                    const int*   __restrict__ y,
                                                    float* __restrict__ out) {
    const int tid    = threadIdx.x;
    const int lane   = tid & 31;
    const int warp   = tid >> 5;          // 0..7
    const int rhalf  = tid >> 7;          // 0/1: which row within block
    const int tid128 = tid & 127;
    const int row    = blockIdx.x * 2 + rhalf;

    const float4 cv = reinterpret_cast<const float4*>(c)[(size_t)row * (COLS / 4) + tid128];
    const int4   yv = reinterpret_cast<const int4*>(y)[(size_t)row * (COLS / 4) + tid128];

    float pos = 0.0f, neg = 0.0f;
    elem(cv.x, yv.x, pos, neg);
    elem(cv.y, yv.y, pos, neg);
    elem(cv.z, yv.z, pos, neg);
    elem(cv.w, yv.w, pos, neg);

    // Label count: 4 ballots + popc (no shuffle chain).
    int ys = __popc(__ballot_sync(0xFFFFFFFFu, yv.x))
           + __popc(__ballot_sync(0xFFFFFFFFu, yv.y))
           + __popc(__ballot_sync(0xFFFFFFFFu, yv.z))
           + __popc(__ballot_sync(0xFFFFFFFFu, yv.w));

    // Two interleaved butterfly chains — latency overlaps.
    #pragma unroll
    for (int o = 16; o > 0; o >>= 1) {
        pos += __shfl_xor_sync(0xFFFFFFFFu, pos, o);
        neg += __shfl_xor_sync(0xFFFFFFFFu, neg, o);
    }

    __shared__ float sp[8];
    __shared__ float sn[8];
    __shared__ int   si[8];
    if (lane == 0) { sp[warp] = pos; sn[warp] = neg; si[warp] = ys; }
    __syncthreads();

    if (tid128 == 0) {  // tid 0 and tid 128: one leader per row
        const int b = rhalf * 4;
        float P = (sp[b] + sp[b + 1]) + (sp[b + 2] + sp[b + 3]);
        float N = (sn[b] + sn[b + 1]) + (sn[b + 2] + sn[b + 3]);
        int   Y = (si[b] + si[b + 1]) + (si[b + 2] + si[b + 3]);
        float part = __fdividef(P * N * E_INV_OVER_ROWS,
                                (float)Y * (float)(COLS - Y));
        asm volatile("red.global.add.f32 [%0], %1;"
                     :: "l"(out), "f"(part) : "memory");
    }
}

extern "C" void kernel_launch(void* const* d_in, const int* in_sizes, int n_in,
                              void* d_out, int out_size) {
    const float* c = (const float*)d_in[0];
    const int*   y = (const int*)d_in[1];
    float*       out = (float*)d_out;
    cudaMemsetAsync(out, 0, sizeof(float));   // graph memset node, ordered before kernel
    bpmll_kernel<<<NBLK, TPB>>>(c, y, out);
}

// round 8
// speedup vs baseline: 1.1893x; 1.1893x over previous
#include <cuda_runtime.h>
#include <cuda_bf16.h>

// BPMLL loss — single graph node, tail-minimized.
//   256 blocks x 256 threads; 128 threads per row (2 rows/block), 4 elems/thread.
//   Row leaders fire red.global.add.f32 into __device__ g_acc (pipelined
//   single-address REDG). An acq_rel counter elects the LAST block, whose
//   thread 0 copies g_acc -> out and resets g_acc/g_count for graph replay.
//   No memset node (each extra graph node costs ~3us wall here), no big
//   winner-phase reduction.
//
// Math per element (2 MUFU + 4 FMA):
//   exp(-sigmoid(c)) = e^{-1} * exp(sigmoid(-c)) -> h(x)=exp(sigmoid(x)),
//   x = y ? -c : c. sigmoid = EX2+RCP; exp(s), s in (0,1), degree-4 poly.

#define ROWS 512
#define COLS 512
#define NBLK 256
#define TPB  256

#define D0 1.00002694f
#define D1 0.99871530f
#define D2 0.50996560f
#define D3 0.13998530f
#define D4 0.06956140f
#define E_INV_OVER_ROWS (0.36787944117144233f / 512.0f)

__device__ float        g_acc   = 0.0f;
__device__ unsigned int g_count = 0;

__device__ __forceinline__ void elem(float c, int y, float& pos, float& neg) {
    float x = __int_as_float(__float_as_int(c) ^ (y << 31));  // y ? -c : c
    float t = __expf(-x);                                     // MUFU.EX2
    float s;
    asm("rcp.approx.f32 %0, %1;" : "=f"(s) : "f"(1.0f + t));  // MUFU.RCP
    float h = fmaf(s, D4, D3);
    h = fmaf(h, s, D2);
    h = fmaf(h, s, D1);
    h = fmaf(h, s, D0);
    if (y) pos += h; else neg += h;
}

__global__ __launch_bounds__(TPB) void bpmll_kernel(const float* __restrict__ c,
                                                    const int*   __restrict__ y,
                                                    float* __restrict__ out) {
    const int tid    = threadIdx.x;
    const int lane   = tid & 31;
    const int warp   = tid >> 5;          // 0..7
    const int rhalf  = tid >> 7;          // 0/1: which row within block
    const int tid128 = tid & 127;
    const int row    = blockIdx.x * 2 + rhalf;

    const float4 cv = reinterpret_cast<const float4*>(c)[(size_t)row * (COLS / 4) + tid128];
    const int4   yv = reinterpret_cast<const int4*>(y)[(size_t)row * (COLS / 4) + tid128];

    float pos = 0.0f, neg = 0.0f;
    elem(cv.x, yv.x, pos, neg);
    elem(cv.y, yv.y, pos, neg);
    elem(cv.z, yv.z, pos, neg);
    elem(cv.w, yv.w, pos, neg);

    // Label count: 4 ballots + popc (no shuffle chain).
    int ys = __popc(__ballot_sync(0xFFFFFFFFu, yv.x))
           + __popc(__ballot_sync(0xFFFFFFFFu, yv.y))
           + __popc(__ballot_sync(0xFFFFFFFFu, yv.z))
           + __popc(__ballot_sync(0xFFFFFFFFu, yv.w));

    // Two interleaved butterfly chains — latency overlaps.
    #pragma unroll
    for (int o = 16; o > 0; o >>= 1) {
        pos += __shfl_xor_sync(0xFFFFFFFFu, pos, o);
        neg += __shfl_xor_sync(0xFFFFFFFFu, neg, o);
    }

    __shared__ float sp[8];
    __shared__ float sn[8];
    __shared__ int   si[8];
    if (lane == 0) { sp[warp] = pos; sn[warp] = neg; si[warp] = ys; }
    __syncthreads();

    if (tid == 0) {
        // Row 0 partial (warps 0-3) and row 1 partial (warps 4-7).
        float P0 = (sp[0] + sp[1]) + (sp[2] + sp[3]);
        float N0 = (sn[0] + sn[1]) + (sn[2] + sn[3]);
        int   Y0 = (si[0] + si[1]) + (si[2] + si[3]);
        float P1 = (sp[4] + sp[5]) + (sp[6] + sp[7]);
        float N1 = (sn[4] + sn[5]) + (sn[6] + sn[7]);
        int   Y1 = (si[4] + si[5]) + (si[6] + si[7]);
        float part = __fdividef(P0 * N0 * E_INV_OVER_ROWS,
                                (float)Y0 * (float)(COLS - Y0))
                   + __fdividef(P1 * N1 * E_INV_OVER_ROWS,
                                (float)Y1 * (float)(COLS - Y1));
        // Fire-and-forget accumulate (no return, pipelined at L2).
        asm volatile("red.global.add.f32 [%0], %1;"
                     :: "l"(&g_acc), "f"(part) : "memory");
        // Release: orders the RED above before the counter bump.
        unsigned int old;
        asm volatile("atom.acq_rel.gpu.global.add.u32 %0, [%1], %2;"
                     : "=r"(old) : "l"(&g_count), "r"(1u) : "memory");
        if (old == (unsigned)(NBLK - 1)) {
            // Last block: acquire above orders this read after all REDs.
            float total;
            asm volatile("ld.global.cg.f32 %0, [%1];" : "=f"(total) : "l"(&g_acc));
            out[0] = total;
            // Reset for next graph replay (kernel boundary orders vs next launch).
            asm volatile("st.global.cg.f32 [%0], %1;" :: "l"(&g_acc), "f"(0.0f) : "memory");
            asm volatile("st.global.cg.u32 [%0], %1;" :: "l"(&g_count), "r"(0u) : "memory");
        }
    }
}

extern "C" void kernel_launch(void* const* d_in, const int* in_sizes, int n_in,
                              void* d_out, int out_size) {
    const float* c = (const float*)d_in[0];
    const int*   y = (const int*)d_in[1];
    float*       out = (float*)d_out;
    bpmll_kernel<<<NBLK, TPB>>>(c, y, out);
}